// round 11
// baseline (speedup 1.0000x reference)
#include <cuda_runtime.h>
#include <cuda_bf16.h>
#include <cstdint>

#define D        64
#define TE       128
#define THREADS  256
#define NMAX     100352     // max nodes (problem uses 100000)

#define SWZ(o) ((o) ^ (((o) >> 3) & 0x70))

// Pre-split, per-lane-fragment-ordered weights: [r][kblk][nblk][lane] = {bh0,bh1,bl0,bl1}
__device__ uint4 g_Wfrag[8][4][8][32];

// Pre-split feature table: hi/lo bf16, [node][64], row = 128B = one cache line.
__device__ __align__(16) __nv_bfloat16 g_Xh[NMAX * D];   // 12.8MB
__device__ __align__(16) __nv_bfloat16 g_Xl[NMAX * D];   // 12.8MB

static __device__ __forceinline__ uint32_t pack_bf16(float lo, float hi) {
    __nv_bfloat162 v = __floats2bfloat162_rn(lo, hi);   // .x = lo (low 16 bits)
    return *reinterpret_cast<uint32_t*>(&v);
}

// Fused prep: blocks [0, R) build W fragments; blocks [R, ...) zero the output
// AND hi/lo-split the feature table (both bandwidth-bound grid-stride loops).
__global__ void prep_and_zero(const float* __restrict__ W,
                              const float4* __restrict__ featv, int nfeat4,
                              float4* __restrict__ outv, int n4, int R)
{
    if (blockIdx.x < (unsigned)R) {
        const int r = blockIdx.x;
        const int t = threadIdx.x;             // 256 threads
        const int nblk = (t >> 5) & 7;
        const int lane = t & 31;
        const int n  = nblk * 8 + (lane >> 2);
        const int t2 = (lane & 3) * 2;
        for (int kblk = 0; kblk < 4; kblk++) {
            const int k0 = kblk * 16;
            float w[4];
            w[0] = W[((size_t)r * D + k0 + t2    ) * D + n];
            w[1] = W[((size_t)r * D + k0 + t2 + 1) * D + n];
            w[2] = W[((size_t)r * D + k0 + t2 + 8) * D + n];
            w[3] = W[((size_t)r * D + k0 + t2 + 9) * D + n];
            float h[4], l[4];
            #pragma unroll
            for (int i = 0; i < 4; i++) {
                h[i] = __bfloat162float(__float2bfloat16(w[i]));
                l[i] = w[i] - h[i];
            }
            g_Wfrag[r][kblk][nblk][lane] =
                make_uint4(pack_bf16(h[0], h[1]), pack_bf16(h[2], h[3]),
                           pack_bf16(l[0], l[1]), pack_bf16(l[2], l[3]));
        }
    } else {
        const int nwb    = gridDim.x - R;
        const int base   = (blockIdx.x - R) * THREADS + threadIdx.x;
        const int stride = nwb * THREADS;

        // zero the output
        const float4 z = make_float4(0.f, 0.f, 0.f, 0.f);
        for (int i = base; i < n4; i += stride) outv[i] = z;

        // hi/lo split of features: one float4 -> uint2 hi + uint2 lo
        uint2* xh = reinterpret_cast<uint2*>(g_Xh);
        uint2* xl = reinterpret_cast<uint2*>(g_Xl);
        for (int i = base; i < nfeat4; i += stride) {
            const float4 v = featv[i];
            const float h0 = __bfloat162float(__float2bfloat16(v.x));
            const float h1 = __bfloat162float(__float2bfloat16(v.y));
            const float h2 = __bfloat162float(__float2bfloat16(v.z));
            const float h3 = __bfloat162float(__float2bfloat16(v.w));
            xh[i] = make_uint2(pack_bf16(h0, h1), pack_bf16(h2, h3));
            xl[i] = make_uint2(pack_bf16(v.x - h0, v.y - h1),
                               pack_bf16(v.z - h2, v.w - h3));
        }
    }
}

static __device__ __forceinline__ uint32_t smem_u32(const void* p) {
    uint32_t a;
    asm("{ .reg .u64 t; cvta.to.shared.u64 t, %1; cvt.u32.u64 %0, t; }" : "=r"(a) : "l"(p));
    return a;
}

#define LDMATRIX_X4(fr, addr)                                              \
    asm volatile("ldmatrix.sync.aligned.m8n8.x4.shared.b16 "               \
                 "{%0, %1, %2, %3}, [%4];"                                 \
                 : "=r"((fr)[0]), "=r"((fr)[1]), "=r"((fr)[2]), "=r"((fr)[3]) \
                 : "r"(addr))

#define MMA_BF16(acc, a, b0, b1)                                           \
    asm volatile("mma.sync.aligned.m16n8k16.row.col.f32.bf16.bf16.f32 "    \
                 "{%0, %1, %2, %3}, {%4, %5, %6, %7}, {%8, %9}, "          \
                 "{%0, %1, %2, %3};"                                       \
                 : "+f"((acc)[0]), "+f"((acc)[1]), "+f"((acc)[2]), "+f"((acc)[3]) \
                 : "r"((a)[0]), "r"((a)[1]), "r"((a)[2]), "r"((a)[3]),     \
                   "r"(b0), "r"(b1))

__global__ __launch_bounds__(THREADS, 3)
void rgcn_hmma_kernel(const int*   __restrict__ edge_src,
                      const int*   __restrict__ edge_dst,
                      float*       __restrict__ out,
                      int E)
{
    __shared__ __align__(1024) __nv_bfloat16 Ah[TE * D];   // 16KB, SW128-swizzled
    __shared__ __align__(1024) __nv_bfloat16 Al[TE * D];   // 16KB

    const int r   = blockIdx.y;
    const int e0  = blockIdx.x * TE;
    const int tid = threadIdx.x;
    const int wid = tid >> 5;
    const int lid = tid & 31;
    const int wm  = wid & 3;     // m 32-slice (edges)
    const int wn  = wid >> 2;    // n 32-slice (outputs)
    const int nE  = min(TE, E - e0);

    char* Ahb = reinterpret_cast<char*>(Ah);
    char* Alb = reinterpret_cast<char*>(Al);

    // ---- prefetch scatter destinations early (independent LDGs) ----
    const int g = lid >> 2;
    int  dn[4];
    bool ok[4];
    #pragma unroll
    for (int rg = 0; rg < 4; rg++) {                 // rg = mt*2 + rh
        const int el = wm * 32 + (rg >> 1) * 16 + (rg & 1) * 8 + g;
        ok[rg] = (el < nE);
        dn[rg] = ok[rg] ? edge_dst[(size_t)r * E + e0 + el] : 0;
    }

    // ---- gather: pure copy of pre-split bf16 rows (no conversion math) ----
    // 8 threads per edge; hi row = 1 line, lo row = 1 line.
    // thread p covers bytes [16p, 16p+16) = elements [8p, 8p+8) of the row.
    {
        const int* srcp = edge_src + (size_t)r * E + e0;
        const int p  = tid & 7;
        const int eb = tid >> 3;           // base edge 0..31
        int s[4];
        #pragma unroll
        for (int ep = 0; ep < 4; ep++) {
            const int e = eb + ep * 32;
            s[ep] = (e < nE) ? srcp[e] : -1;
        }
        #pragma unroll 2
        for (int ep = 0; ep < 4; ep++) {
            const int e = eb + ep * 32;
            const uint32_t o = SWZ((uint32_t)(e * 128 + p * 16));
            if (s[ep] >= 0) {
                const uint4 h = *reinterpret_cast<const uint4*>(g_Xh + (size_t)s[ep] * D + p * 8);
                const uint4 l = *reinterpret_cast<const uint4*>(g_Xl + (size_t)s[ep] * D + p * 8);
                *reinterpret_cast<uint4*>(Ahb + o) = h;
                *reinterpret_cast<uint4*>(Alb + o) = l;
            } else {
                const uint4 z = make_uint4(0u, 0u, 0u, 0u);
                *reinterpret_cast<uint4*>(Ahb + o) = z;
                *reinterpret_cast<uint4*>(Alb + o) = z;
            }
        }
    }
    __syncthreads();

    // ---- HMMA mainloop (round-3 tiling): acc[mt][nb][4], D = Ah*Bh + Al*Bh + Ah*Bl
    float acc[2][4][4];
    #pragma unroll
    for (int mt = 0; mt < 2; mt++)
        #pragma unroll
        for (int nb = 0; nb < 4; nb++)
            #pragma unroll
            for (int j = 0; j < 4; j++) acc[mt][nb][j] = 0.f;

    const uint32_t ah_base = smem_u32(Ah);
    const uint32_t al_base = smem_u32(Al);
    const int lrow = lid & 15;
    const int lkof = (lid >> 4) * 16;

    #pragma unroll
    for (int kblk = 0; kblk < 4; kblk++) {
        uint32_t afh[2][4], afl[2][4];
        #pragma unroll
        for (int mt = 0; mt < 2; mt++) {
            const int row = wm * 32 + mt * 16 + lrow;
            const uint32_t off = SWZ((uint32_t)(row * 128 + kblk * 32 + lkof));
            LDMATRIX_X4(afh[mt], ah_base + off);
            LDMATRIX_X4(afl[mt], al_base + off);
        }
        #pragma unroll
        for (int nb = 0; nb < 4; nb++) {
            const uint4 B = __ldg(&g_Wfrag[r][kblk][wn * 4 + nb][lid]);
            #pragma unroll
            for (int mt = 0; mt < 2; mt++) {
                MMA_BF16(acc[mt][nb], afh[mt], B.x, B.y);
                MMA_BF16(acc[mt][nb], afl[mt], B.x, B.y);
                MMA_BF16(acc[mt][nb], afh[mt], B.z, B.w);
            }
        }
    }

    // ---- scatter: pair-shuffle fragments into 16B runs, red.global.add.v4 ----
    const int  odd      = lid & 1;
    const int  colquad  = ((lid & 2) >> 1) * 4;      // 0 or 4 within n8 block

    #pragma unroll
    for (int mt = 0; mt < 2; mt++) {
        #pragma unroll
        for (int rh = 0; rh < 2; rh++) {
            const int rg = mt * 2 + rh;
            #pragma unroll
            for (int nbp = 0; nbp < 2; nbp++) {
                // even lane emits nb = nbp*2, odd emits nbp*2+1;
                // each sends the partner's nb, receives its missing half.
                const float s0 = odd ? acc[mt][nbp * 2][rh * 2]
                                     : acc[mt][nbp * 2 + 1][rh * 2];
                const float s1 = odd ? acc[mt][nbp * 2][rh * 2 + 1]
                                     : acc[mt][nbp * 2 + 1][rh * 2 + 1];
                const float m0 = odd ? acc[mt][nbp * 2 + 1][rh * 2]
                                     : acc[mt][nbp * 2][rh * 2];
                const float m1 = odd ? acc[mt][nbp * 2 + 1][rh * 2 + 1]
                                     : acc[mt][nbp * 2][rh * 2 + 1];
                const float r0 = __shfl_xor_sync(0xffffffffu, s0, 1);
                const float r1 = __shfl_xor_sync(0xffffffffu, s1, 1);

                // even lane owns lower t2 -> (mine, recv); odd -> (recv, mine)
                const float v0 = odd ? r0 : m0;
                const float v1 = odd ? r1 : m1;
                const float v2 = odd ? m0 : r0;
                const float v3 = odd ? m1 : r1;

                if (ok[rg]) {
                    const int col = wn * 32 + (nbp * 2 + odd) * 8 + colquad;
                    float* o = out + (size_t)dn[rg] * D + col;   // 16B aligned
                    asm volatile("red.global.add.v4.f32 [%0], {%1, %2, %3, %4};"
                                 :: "l"(o), "f"(v0), "f"(v1), "f"(v2), "f"(v3)
                                 : "memory");
                }
            }
        }
    }
}

extern "C" void kernel_launch(void* const* d_in, const int* in_sizes, int n_in,
                              void* d_out, int out_size)
{
    const float* feat     = (const float*)d_in[0];
    const float* weight   = (const float*)d_in[1];
    const int*   edge_src = (const int*)d_in[2];
    const int*   edge_dst = (const int*)d_in[3];
    float*       out      = (float*)d_out;

    const int R = in_sizes[1] / (D * D);     // 8
    const int E = in_sizes[2] / R;           // 100000
    const int nfeat4 = in_sizes[0] / 4;      // feat as float4 count

    // fused W-prep + output zeroing + feature hi/lo pre-split
    prep_and_zero<<<R + 2048, THREADS>>>(weight, (const float4*)feat, nfeat4,
                                         (float4*)d_out, out_size / 4, R);

    dim3 grid((E + TE - 1) / TE, R);
    rgcn_hmma_kernel<<<grid, THREADS>>>(edge_src, edge_dst, out, E);
}

// round 12
// speedup vs baseline: 1.0648x; 1.0648x over previous
#include <cuda_runtime.h>
#include <cuda_bf16.h>
#include <cstdint>

#define D        64
#define TE       128          // edges per tile
#define TILE2    256          // edges per block = 2 tiles, double-buffered
#define THREADS  256
#define NMAX     100352       // max nodes (problem uses 100000); last row = zero row
#define ZROW     (NMAX - 1)

#define SWZ(o) ((o) ^ (((o) >> 3) & 0x70))

// Pre-split, per-lane-fragment-ordered weights: [r][kblk][nblk][lane] = {bh0,bh1,bl0,bl1}
__device__ uint4 g_Wfrag[8][4][8][32];

// Pre-split feature table: hi/lo bf16, [node][64], row = 128B.
__device__ __align__(16) __nv_bfloat16 g_Xh[NMAX * D];   // 12.8MB
__device__ __align__(16) __nv_bfloat16 g_Xl[NMAX * D];   // 12.8MB

static __device__ __forceinline__ uint32_t pack_bf16(float lo, float hi) {
    __nv_bfloat162 v = __floats2bfloat162_rn(lo, hi);   // .x = lo (low 16 bits)
    return *reinterpret_cast<uint32_t*>(&v);
}

// Fused prep: blocks [0, R) build W fragments; blocks [R, ...) zero the output
// and hi/lo-split the feature table (incl. zero padding rows up to NMAX).
__global__ void prep_and_zero(const float* __restrict__ W,
                              const float4* __restrict__ featv, int nfeat4,
                              float4* __restrict__ outv, int n4, int R)
{
    if (blockIdx.x < (unsigned)R) {
        const int r = blockIdx.x;
        const int t = threadIdx.x;             // 256 threads
        const int nblk = (t >> 5) & 7;
        const int lane = t & 31;
        const int n  = nblk * 8 + (lane >> 2);
        const int t2 = (lane & 3) * 2;
        for (int kblk = 0; kblk < 4; kblk++) {
            const int k0 = kblk * 16;
            float w[4];
            w[0] = W[((size_t)r * D + k0 + t2    ) * D + n];
            w[1] = W[((size_t)r * D + k0 + t2 + 1) * D + n];
            w[2] = W[((size_t)r * D + k0 + t2 + 8) * D + n];
            w[3] = W[((size_t)r * D + k0 + t2 + 9) * D + n];
            float h[4], l[4];
            #pragma unroll
            for (int i = 0; i < 4; i++) {
                h[i] = __bfloat162float(__float2bfloat16(w[i]));
                l[i] = w[i] - h[i];
            }
            g_Wfrag[r][kblk][nblk][lane] =
                make_uint4(pack_bf16(h[0], h[1]), pack_bf16(h[2], h[3]),
                           pack_bf16(l[0], l[1]), pack_bf16(l[2], l[3]));
        }
    } else {
        const int nwb    = gridDim.x - R;
        const int base   = (blockIdx.x - R) * THREADS + threadIdx.x;
        const int stride = nwb * THREADS;

        // zero the output
        const float4 z = make_float4(0.f, 0.f, 0.f, 0.f);
        for (int i = base; i < n4; i += stride) outv[i] = z;

        // hi/lo split of features: one float4 -> uint2 hi + uint2 lo
        uint2* xh = reinterpret_cast<uint2*>(g_Xh);
        uint2* xl = reinterpret_cast<uint2*>(g_Xl);
        for (int i = base; i < nfeat4; i += stride) {
            const float4 v = featv[i];
            const float h0 = __bfloat162float(__float2bfloat16(v.x));
            const float h1 = __bfloat162float(__float2bfloat16(v.y));
            const float h2 = __bfloat162float(__float2bfloat16(v.z));
            const float h3 = __bfloat162float(__float2bfloat16(v.w));
            xh[i] = make_uint2(pack_bf16(h0, h1), pack_bf16(h2, h3));
            xl[i] = make_uint2(pack_bf16(v.x - h0, v.y - h1),
                               pack_bf16(v.z - h2, v.w - h3));
        }
        // zero padding rows (covers ZROW used for OOB edges)
        const uint2 z2 = make_uint2(0u, 0u);
        for (int i = nfeat4 + base; i < NMAX * (D / 4); i += stride) {
            xh[i] = z2;
            xl[i] = z2;
        }
    }
}

static __device__ __forceinline__ uint32_t smem_u32(const void* p) {
    uint32_t a;
    asm("{ .reg .u64 t; cvta.to.shared.u64 t, %1; cvt.u32.u64 %0, t; }" : "=r"(a) : "l"(p));
    return a;
}

#define CP_ASYNC16(dst_u32, src_ptr)                                       \
    asm volatile("cp.async.cg.shared.global [%0], [%1], 16;"               \
                 :: "r"(dst_u32), "l"(src_ptr) : "memory")
#define CP_COMMIT()  asm volatile("cp.async.commit_group;" ::: "memory")
#define CP_WAIT(n)   asm volatile("cp.async.wait_group %0;" :: "n"(n) : "memory")

#define LDMATRIX_X4(fr, addr)                                              \
    asm volatile("ldmatrix.sync.aligned.m8n8.x4.shared.b16 "               \
                 "{%0, %1, %2, %3}, [%4];"                                 \
                 : "=r"((fr)[0]), "=r"((fr)[1]), "=r"((fr)[2]), "=r"((fr)[3]) \
                 : "r"(addr))

#define MMA_BF16(acc, a, b0, b1)                                           \
    asm volatile("mma.sync.aligned.m16n8k16.row.col.f32.bf16.bf16.f32 "    \
                 "{%0, %1, %2, %3}, {%4, %5, %6, %7}, {%8, %9}, "          \
                 "{%0, %1, %2, %3};"                                       \
                 : "+f"((acc)[0]), "+f"((acc)[1]), "+f"((acc)[2]), "+f"((acc)[3]) \
                 : "r"((a)[0]), "r"((a)[1]), "r"((a)[2]), "r"((a)[3]),     \
                   "r"(b0), "r"(b1))

// Issue the cp.async gather for one 128-edge tile into (ah, al) buffers.
static __device__ __forceinline__ void issue_gather(
    uint32_t ah_u32, uint32_t al_u32,
    const int* __restrict__ srcp, int nEt, int tid)
{
    const int p  = tid & 7;
    const int eb = tid >> 3;           // base edge 0..31
    #pragma unroll
    for (int ep = 0; ep < 4; ep++) {
        const int e = eb + ep * 32;
        const int s = (e < nEt) ? srcp[e] : ZROW;
        const uint32_t o = SWZ((uint32_t)(e * 128 + p * 16));
        CP_ASYNC16(ah_u32 + o, g_Xh + (size_t)s * D + p * 8);
        CP_ASYNC16(al_u32 + o, g_Xl + (size_t)s * D + p * 8);
    }
}

// Compute one 128-edge tile (round-3 tiling) and scatter it.
static __device__ __forceinline__ void tile_compute(
    uint32_t ah_base, uint32_t al_base,
    int r, const int* __restrict__ dstp, int nEt,
    float* __restrict__ out, int wm, int wn, int lid)
{
    float acc[2][4][4];
    #pragma unroll
    for (int mt = 0; mt < 2; mt++)
        #pragma unroll
        for (int nb = 0; nb < 4; nb++)
            #pragma unroll
            for (int j = 0; j < 4; j++) acc[mt][nb][j] = 0.f;

    const int lrow = lid & 15;
    const int lkof = (lid >> 4) * 16;

    #pragma unroll
    for (int kblk = 0; kblk < 4; kblk++) {
        uint32_t afh[2][4], afl[2][4];
        #pragma unroll
        for (int mt = 0; mt < 2; mt++) {
            const int row = wm * 32 + mt * 16 + lrow;
            const uint32_t off = SWZ((uint32_t)(row * 128 + kblk * 32 + lkof));
            LDMATRIX_X4(afh[mt], ah_base + off);
            LDMATRIX_X4(afl[mt], al_base + off);
        }
        #pragma unroll
        for (int nb = 0; nb < 4; nb++) {
            const uint4 B = __ldg(&g_Wfrag[r][kblk][wn * 4 + nb][lid]);
            #pragma unroll
            for (int mt = 0; mt < 2; mt++) {
                MMA_BF16(acc[mt][nb], afh[mt], B.x, B.y);
                MMA_BF16(acc[mt][nb], afl[mt], B.x, B.y);
                MMA_BF16(acc[mt][nb], afh[mt], B.z, B.w);
            }
        }
    }

    // scatter destinations
    const int g = lid >> 2;
    int  dn[4];
    bool ok[4];
    #pragma unroll
    for (int rg = 0; rg < 4; rg++) {                 // rg = mt*2 + rh
        const int el = wm * 32 + (rg >> 1) * 16 + (rg & 1) * 8 + g;
        ok[rg] = (el < nEt);
        dn[rg] = ok[rg] ? dstp[el] : 0;
    }

    const int odd     = lid & 1;
    const int colquad = ((lid & 2) >> 1) * 4;        // 0 or 4 within n8 block

    #pragma unroll
    for (int mt = 0; mt < 2; mt++) {
        #pragma unroll
        for (int rh = 0; rh < 2; rh++) {
            const int rg = mt * 2 + rh;
            #pragma unroll
            for (int nbp = 0; nbp < 2; nbp++) {
                const float s0 = odd ? acc[mt][nbp * 2][rh * 2]
                                     : acc[mt][nbp * 2 + 1][rh * 2];
                const float s1 = odd ? acc[mt][nbp * 2][rh * 2 + 1]
                                     : acc[mt][nbp * 2 + 1][rh * 2 + 1];
                const float m0 = odd ? acc[mt][nbp * 2 + 1][rh * 2]
                                     : acc[mt][nbp * 2][rh * 2];
                const float m1 = odd ? acc[mt][nbp * 2 + 1][rh * 2 + 1]
                                     : acc[mt][nbp * 2][rh * 2 + 1];
                const float r0 = __shfl_xor_sync(0xffffffffu, s0, 1);
                const float r1 = __shfl_xor_sync(0xffffffffu, s1, 1);

                const float v0 = odd ? r0 : m0;
                const float v1 = odd ? r1 : m1;
                const float v2 = odd ? m0 : r0;
                const float v3 = odd ? m1 : r1;

                if (ok[rg]) {
                    const int col = wn * 32 + (nbp * 2 + odd) * 8 + colquad;
                    float* o = out + (size_t)dn[rg] * D + col;   // 16B aligned
                    asm volatile("red.global.add.v4.f32 [%0], {%1, %2, %3, %4};"
                                 :: "l"(o), "f"(v0), "f"(v1), "f"(v2), "f"(v3)
                                 : "memory");
                }
            }
        }
    }
}

// dynamic smem layout: [Ah0 | Al0 | Ah1 | Al1], 16KB each, 64KB total
#define SMEM_BYTES (4 * TE * D * 2)

__global__ __launch_bounds__(THREADS, 3)
void rgcn_hmma_kernel(const int* __restrict__ edge_src,
                      const int* __restrict__ edge_dst,
                      float*     __restrict__ out,
                      int E)
{
    extern __shared__ __align__(1024) char smem[];
    const uint32_t sb  = smem_u32(smem);
    const uint32_t ah0 = sb;
    const uint32_t al0 = sb + 16384;
    const uint32_t ah1 = sb + 32768;
    const uint32_t al1 = sb + 49152;

    const int r   = blockIdx.y;
    const int e0  = blockIdx.x * TILE2;
    const int tid = threadIdx.x;
    const int wid = tid >> 5;
    const int lid = tid & 31;
    const int wm  = wid & 3;     // m 32-slice (edges)
    const int wn  = wid >> 2;    // n 32-slice (outputs)
    const int nE  = E - e0;      // >= 1
    const int nE0 = min(TE, nE);
    const int nE1 = min(TE, nE - TE);    // may be <= 0

    const int* srcp = edge_src + (size_t)r * E + e0;
    const int* dstp = edge_dst + (size_t)r * E + e0;

    // issue both tiles' gathers up front (2 commit groups)
    issue_gather(ah0, al0, srcp, nE0, tid);
    CP_COMMIT();
    issue_gather(ah1, al1, srcp + TE, nE1, tid);
    CP_COMMIT();

    // tile 0: wait only for group 0; tile 1's copies overlap tile-0 compute
    CP_WAIT(1);
    __syncthreads();
    tile_compute(ah0, al0, r, dstp, nE0, out, wm, wn, lid);

    CP_WAIT(0);
    __syncthreads();
    if (nE1 > 0)
        tile_compute(ah1, al1, r, dstp + TE, nE1, out, wm, wn, lid);
}

extern "C" void kernel_launch(void* const* d_in, const int* in_sizes, int n_in,
                              void* d_out, int out_size)
{
    const float* feat     = (const float*)d_in[0];
    const float* weight   = (const float*)d_in[1];
    const int*   edge_src = (const int*)d_in[2];
    const int*   edge_dst = (const int*)d_in[3];
    float*       out      = (float*)d_out;

    const int R = in_sizes[1] / (D * D);     // 8
    const int E = in_sizes[2] / R;           // 100000
    const int nfeat4 = in_sizes[0] / 4;      // feat as float4 count

    // fused W-prep + output zeroing + feature hi/lo pre-split
    prep_and_zero<<<R + 2048, THREADS>>>(weight, (const float4*)feat, nfeat4,
                                         (float4*)d_out, out_size / 4, R);

    cudaFuncSetAttribute(rgcn_hmma_kernel,
                         cudaFuncAttributeMaxDynamicSharedMemorySize, SMEM_BYTES);

    dim3 grid((E + TILE2 - 1) / TILE2, R);
    rgcn_hmma_kernel<<<grid, THREADS, SMEM_BYTES>>>(edge_src, edge_dst, out, E);
}